// round 9
// baseline (speedup 1.0000x reference)
#include <cuda_runtime.h>
#include <math.h>

// Problem constants
#define B_    2
#define C_    128
#define NN    784
#define INVT  0.08838834764831845f   // 1/sqrt(128)
#define INVC  0.0078125f             // 1/128

typedef unsigned long long ull;
#define ABS2MASK 0x7FFFFFFF7FFFFFFFULL

// ================= Distance kernel: attn[b,k,q] = mean_c |q/T - k| =============
// Packed f32x2. qS holds q/T (packed along q); kS2 holds -k duplicated as pairs.
// Per packed update: FADD2 diff (fma) + 64-bit AND (2x LOP3, alu) + FADD2 acc (fma)
// -> work split evenly across fma/alu pipes, ~2x the scalar FADD throughput.
// Tile 64q x 32k, 64 threads, micro 8q x 4k per thread. 650 blocks.
#define DQT  64
#define DKT  32
#define DCS  64
#define QLD  68     // 64 + 4 pad floats
#define KLD  68     // 64 (32 k duplicated) + 4 pad floats

__global__ __launch_bounds__(64) void dist_kernel(const float* __restrict__ q,
                                                  const float* __restrict__ k,
                                                  float* __restrict__ attn) {
    __shared__ float qS[DCS * QLD];
    __shared__ float kS[DCS * KLD];
    const int qt = blockIdx.x * DQT;
    const int kt = blockIdx.y * DKT;
    const int b  = blockIdx.z;
    const int tid = threadIdx.x;
    const int tx = tid & 7;     // q micro: tx*8 .. +7  (4 packed pairs)
    const int ty = tid >> 3;    // k micro: ty*4 .. +3

    const float* qb = q + (size_t)b * C_ * NN;
    const float* kb = k + (size_t)b * C_ * NN;

    ull acc[4][4];              // [k j][q pair p]
    #pragma unroll
    for (int j = 0; j < 4; j++)
        #pragma unroll
        for (int p = 0; p < 4; p++) acc[j][p] = 0ULL;

    #pragma unroll
    for (int cc = 0; cc < C_; cc += DCS) {
        // stage q (scaled): 64c x 16 float4 = 1024 float4 over 64 threads
        #pragma unroll
        for (int t = 0; t < 16; t++) {
            int i = tid + t * 64;
            int c = i >> 4, col = i & 15;
            int gq = qt + col * 4;
            float4 qv = make_float4(0.f, 0.f, 0.f, 0.f);
            if (gq < NN) qv = *(const float4*)&qb[(size_t)(cc + c) * NN + gq];
            qv.x *= INVT; qv.y *= INVT; qv.z *= INVT; qv.w *= INVT;
            *(float4*)&qS[c * QLD + col * 4] = qv;
        }
        // stage k (negated + duplicated pairs): 64c x 8 float4 = 512 over 64 thr
        #pragma unroll
        for (int t = 0; t < 8; t++) {
            int i = tid + t * 64;
            int c = i >> 3, col = i & 7;
            int gk = kt + col * 4;
            float4 kv = make_float4(0.f, 0.f, 0.f, 0.f);
            if (gk < NN) kv = *(const float4*)&kb[(size_t)(cc + c) * NN + gk];
            float2* kr = (float2*)&kS[c * KLD + col * 8];
            kr[0] = make_float2(-kv.x, -kv.x);
            kr[1] = make_float2(-kv.y, -kv.y);
            kr[2] = make_float2(-kv.z, -kv.z);
            kr[3] = make_float2(-kv.w, -kv.w);
        }
        __syncthreads();

        #pragma unroll 4
        for (int c = 0; c < DCS; c++) {
            const ull* qrow = (const ull*)&qS[c * QLD + tx * 8];
            ull qp[4];
            qp[0] = qrow[0]; qp[1] = qrow[1]; qp[2] = qrow[2]; qp[3] = qrow[3];
            #pragma unroll
            for (int j = 0; j < 4; j++) {
                const ull kp = *(const ull*)&kS[c * KLD + (ty * 4 + j) * 2];
                #pragma unroll
                for (int p = 0; p < 4; p++) {
                    ull d;
                    asm("add.rn.f32x2 %0, %1, %2;" : "=l"(d) : "l"(qp[p]), "l"(kp));
                    d &= ABS2MASK;
                    asm("add.rn.f32x2 %0, %0, %1;" : "+l"(acc[j][p]) : "l"(d));
                }
            }
        }
        __syncthreads();
    }

    float* ab = attn + (size_t)b * NN * NN;
    // 784 % 8 == 0 -> each float4 (4 consecutive q) is all-valid or all-invalid
    #pragma unroll
    for (int j = 0; j < 4; j++) {
        int gk = kt + ty * 4 + j;
        if (gk < NN) {
            float* row = &ab[(size_t)gk * NN + qt + tx * 8];
            #pragma unroll
            for (int h = 0; h < 2; h++) {
                int gq = qt + tx * 8 + h * 4;
                if (gq < NN) {
                    float4 o;
                    o.x = __uint_as_float((unsigned)(acc[j][2*h]   & 0xffffffffu)) * INVC;
                    o.y = __uint_as_float((unsigned)(acc[j][2*h]   >> 32))         * INVC;
                    o.z = __uint_as_float((unsigned)(acc[j][2*h+1] & 0xffffffffu)) * INVC;
                    o.w = __uint_as_float((unsigned)(acc[j][2*h+1] >> 32))         * INVC;
                    *(float4*)&row[h * 4] = o;
                }
            }
        }
    }
}

// ================= Softmax over last dim (q), in place ========================
__global__ __launch_bounds__(256) void softmax_kernel(float* __restrict__ attn) {
    __shared__ float red[8];
    const int row = blockIdx.x;
    float* p = attn + (size_t)row * NN;
    const int tid  = threadIdx.x;
    const bool act = (tid < NN / 4);   // 196 active lanes

    float4 v = make_float4(-1e30f, -1e30f, -1e30f, -1e30f);
    if (act) v = ((const float4*)p)[tid];

    float mx = fmaxf(fmaxf(v.x, v.y), fmaxf(v.z, v.w));
    #pragma unroll
    for (int o = 16; o > 0; o >>= 1) mx = fmaxf(mx, __shfl_xor_sync(0xffffffffu, mx, o));
    if ((tid & 31) == 0) red[tid >> 5] = mx;
    __syncthreads();
    if (tid < 32) {
        float m = (tid < 8) ? red[tid] : -1e30f;
        #pragma unroll
        for (int o = 4; o > 0; o >>= 1) m = fmaxf(m, __shfl_xor_sync(0xffffffffu, m, o));
        if (tid == 0) red[0] = m;
    }
    __syncthreads();
    mx = red[0];
    __syncthreads();

    v.x = __expf(v.x - mx); v.y = __expf(v.y - mx);
    v.z = __expf(v.z - mx); v.w = __expf(v.w - mx);
    float s = act ? (v.x + v.y) + (v.z + v.w) : 0.f;
    #pragma unroll
    for (int o = 16; o > 0; o >>= 1) s += __shfl_xor_sync(0xffffffffu, s, o);
    if ((tid & 31) == 0) red[tid >> 5] = s;
    __syncthreads();
    if (tid < 32) {
        float m = (tid < 8) ? red[tid] : 0.f;
        #pragma unroll
        for (int o = 4; o > 0; o >>= 1) m += __shfl_xor_sync(0xffffffffu, m, o);
        if (tid == 0) red[0] = m;
    }
    __syncthreads();
    const float inv = 1.f / red[0];
    if (act) {
        v.x *= inv; v.y *= inv; v.z *= inv; v.w *= inv;
        ((float4*)p)[tid] = v;
    }
}

// ================= GEMM: out[b,c,k] = sum_q v[b,c,q] * attn[b,k,q] ============
#define GTHR   224
#define GTN    112
#define GBQ    16
#define NSPLIT 21
#define NCH    49          // 784/16 q-chunks
#define VLDg   132         // 128 + 4
#define ALDg   116         // 112 + 4
#define PTILE  (128 * 112) // 14336

__device__ float g_part[(size_t)B_ * NSPLIT * 7 * PTILE];

__global__ __launch_bounds__(GTHR) void gemm1_kernel(const float* __restrict__ v,
                                                     const float* __restrict__ attn) {
    __shared__ float vS[GBQ * VLDg];   // [q][c]
    __shared__ float aS[GBQ * ALDg];   // [q][k]
    const int ktile = blockIdx.x;      // 0..6
    const int s     = blockIdx.y;      // 0..20
    const int b     = blockIdx.z;
    const int tid = threadIdx.x;
    const int tx = tid % 28;           // k: tx*4 .. +3
    const int ty = tid / 28;           // c: ty*16 .. +15

    const float* vb = v    + (size_t)b * C_ * NN;
    const float* ab = attn + (size_t)b * NN * NN + (size_t)ktile * GTN * NN;

    ull acc[8][4];
    #pragma unroll
    for (int p = 0; p < 8; p++)
        #pragma unroll
        for (int j = 0; j < 4; j++) acc[p][j] = 0ULL;

    const int ch0 = (s * NCH) / NSPLIT;
    const int ch1 = ((s + 1) * NCH) / NSPLIT;

    for (int ch = ch0; ch < ch1; ch++) {
        const int q0 = ch * GBQ;
        for (int i = tid; i < 512; i += GTHR) {
            int c = i >> 2, q4 = i & 3;
            float4 t = *(const float4*)&vb[(size_t)c * NN + q0 + q4 * 4];
            vS[(q4 * 4 + 0) * VLDg + c] = t.x;
            vS[(q4 * 4 + 1) * VLDg + c] = t.y;
            vS[(q4 * 4 + 2) * VLDg + c] = t.z;
            vS[(q4 * 4 + 3) * VLDg + c] = t.w;
        }
        for (int i = tid; i < 448; i += GTHR) {
            int kk = i >> 2, q4 = i & 3;
            float4 t = *(const float4*)&ab[(size_t)kk * NN + q0 + q4 * 4];
            aS[(q4 * 4 + 0) * ALDg + kk] = t.x;
            aS[(q4 * 4 + 1) * ALDg + kk] = t.y;
            aS[(q4 * 4 + 2) * ALDg + kk] = t.z;
            aS[(q4 * 4 + 3) * ALDg + kk] = t.w;
        }
        __syncthreads();

        #pragma unroll 4
        for (int qq = 0; qq < GBQ; qq++) {
            float4 a4 = *(const float4*)&aS[qq * ALDg + tx * 4];
            ull d[4];
            asm("mov.b64 %0, {%1, %1};" : "=l"(d[0]) : "f"(a4.x));
            asm("mov.b64 %0, {%1, %1};" : "=l"(d[1]) : "f"(a4.y));
            asm("mov.b64 %0, {%1, %1};" : "=l"(d[2]) : "f"(a4.z));
            asm("mov.b64 %0, {%1, %1};" : "=l"(d[3]) : "f"(a4.w));
            const float* vrow = &vS[qq * VLDg + ty * 16];
            float4 v0 = *(const float4*)(vrow + 0);
            float4 v1 = *(const float4*)(vrow + 4);
            float4 v2 = *(const float4*)(vrow + 8);
            float4 v3 = *(const float4*)(vrow + 12);
            ull vp[8];
            vp[0] = ((const ull*)&v0)[0]; vp[1] = ((const ull*)&v0)[1];
            vp[2] = ((const ull*)&v1)[0]; vp[3] = ((const ull*)&v1)[1];
            vp[4] = ((const ull*)&v2)[0]; vp[5] = ((const ull*)&v2)[1];
            vp[6] = ((const ull*)&v3)[0]; vp[7] = ((const ull*)&v3)[1];
            #pragma unroll
            for (int p = 0; p < 8; p++) {
                #pragma unroll
                for (int j = 0; j < 4; j++)
                    asm("fma.rn.f32x2 %0, %1, %2, %0;"
                        : "+l"(acc[p][j]) : "l"(vp[p]), "l"(d[j]));
            }
        }
        __syncthreads();
    }

    float* base = g_part + (((size_t)(b * NSPLIT + s) * 7) + ktile) * PTILE;
    #pragma unroll
    for (int p = 0; p < 8; p++) {
        int c0 = ty * 16 + p * 2;
        float4 lo, hi;
        lo.x = __uint_as_float((unsigned)(acc[p][0] & 0xffffffffu));
        lo.y = __uint_as_float((unsigned)(acc[p][1] & 0xffffffffu));
        lo.z = __uint_as_float((unsigned)(acc[p][2] & 0xffffffffu));
        lo.w = __uint_as_float((unsigned)(acc[p][3] & 0xffffffffu));
        hi.x = __uint_as_float((unsigned)(acc[p][0] >> 32));
        hi.y = __uint_as_float((unsigned)(acc[p][1] >> 32));
        hi.z = __uint_as_float((unsigned)(acc[p][2] >> 32));
        hi.w = __uint_as_float((unsigned)(acc[p][3] >> 32));
        *(float4*)&base[(size_t)c0 * GTN + tx * 4]       = lo;
        *(float4*)&base[(size_t)(c0 + 1) * GTN + tx * 4] = hi;
    }
}

__global__ __launch_bounds__(256) void gemm2_kernel(float* __restrict__ out) {
    const int idx = blockIdx.x * 256 + threadIdx.x;   // float4 index
    const int total4 = B_ * C_ * NN / 4;              // 50176
    if (idx >= total4) return;
    const int per_b = C_ * NN / 4;
    const int b = idx / per_b;
    const int e = (idx % per_b) * 4;
    const int c  = e / NN;
    const int kk = e % NN;
    const int kt = kk / GTN, kl = kk % GTN;
    const float* src = g_part + (((size_t)(b * NSPLIT) * 7) + kt) * PTILE
                     + (size_t)c * GTN + kl;
    float4 s = make_float4(0.f, 0.f, 0.f, 0.f);
    #pragma unroll
    for (int sp = 0; sp < NSPLIT; sp++) {
        float4 t = *(const float4*)(src + (size_t)sp * 7 * PTILE);
        s.x += t.x; s.y += t.y; s.z += t.z; s.w += t.w;
    }
    ((float4*)out)[idx] = s;
}

// ================= Launch ======================================================
extern "C" void kernel_launch(void* const* d_in, const int* in_sizes, int n_in,
                              void* d_out, int out_size) {
    const float* q = (const float*)d_in[0];
    const float* k = (const float*)d_in[1];
    const float* v = (const float*)d_in[2];
    float* out  = (float*)d_out;                      // [B, C, N]
    float* attn = out + (size_t)B_ * C_ * NN;         // [B, N, N]

    (void)in_sizes; (void)n_in; (void)out_size;

    // 1) L1 distance logits -> attn region (13 x 25 x 2 = 650 blocks)
    dim3 dgrid((NN + DQT - 1) / DQT, (NN + DKT - 1) / DKT, B_);
    dist_kernel<<<dgrid, 64>>>(q, k, attn);

    // 2) softmax over q, in place
    softmax_kernel<<<B_ * NN, 256>>>(attn);

    // 3) out = v @ attn^T : split-q partials, then reduce
    dim3 g1(7, NSPLIT, B_);                           // 294 blocks
    gemm1_kernel<<<g1, GTHR>>>(v, attn);
    gemm2_kernel<<<(B_ * C_ * NN / 4 + 255) / 256, 256>>>(out);
}

// round 10
// speedup vs baseline: 1.1353x; 1.1353x over previous
#include <cuda_runtime.h>
#include <math.h>

// Problem constants
#define B_    2
#define C_    128
#define NN    784
#define INVT  0.08838834764831845f   // 1/sqrt(128)
#define INVC  0.0078125f             // 1/128

typedef unsigned long long ull;
#define ABS2MASK 0x7FFFFFFF7FFFFFFFULL

// ================= Distance kernel: attn[b,k,q] = mean_c |q/T - k| =============
// R8 geometry (32x32 tiles, 64 threads, 4q x 4k micro) with an FFMA2-packed
// inner loop:  d = fma.f32x2(q, INVT2, -k)  ;  |d| = and.b64  ;
//              acc = fma.f32x2(|d|, ONE2, acc).
// Per 2 elems: 2 FFMA2 (fma pipe) + 2 LOP3 (alu pipe), overlapped -> ~2x scalar.
#define DQT 32
#define DKT 32
#define DCS 64
#define DLD 36   // 32 + 4 pad

__global__ __launch_bounds__(64) void dist_kernel(const float* __restrict__ q,
                                                  const float* __restrict__ k,
                                                  float* __restrict__ attn) {
    __shared__ float qS[DCS * DLD];
    __shared__ float kS[DCS * DLD];
    const int qt = blockIdx.x * DQT;
    const int kt = blockIdx.y * DKT;
    const int b  = blockIdx.z;
    const int tid = threadIdx.x;
    const int tx = tid & 7;     // q micro: tx*4 .. +3  (2 packed pairs)
    const int ty = tid >> 3;    // k micro: ty*4 .. +3

    const float* qb = q + (size_t)b * C_ * NN;
    const float* kb = k + (size_t)b * C_ * NN;

    ull INVT2, ONE2;
    asm("mov.b64 %0, {%1, %1};" : "=l"(INVT2) : "f"(INVT));
    asm("mov.b64 %0, {%1, %1};" : "=l"(ONE2)  : "f"(1.0f));

    ull acc[4][2];              // [k j][q pair p]
    #pragma unroll
    for (int j = 0; j < 4; j++) { acc[j][0] = 0ULL; acc[j][1] = 0ULL; }

    #pragma unroll
    for (int cc = 0; cc < C_; cc += DCS) {
        // stage q tile (raw): 64c x 8 float4 = 512 float4 over 64 threads
        #pragma unroll
        for (int t = 0; t < 8; t++) {
            int i = tid + t * 64;
            int c = i >> 3, col = i & 7;
            int gq = qt + col * 4;
            float4 qv = make_float4(0.f, 0.f, 0.f, 0.f);
            if (gq < NN) qv = *(const float4*)&qb[(size_t)(cc + c) * NN + gq];
            *(float4*)&qS[c * DLD + col * 4] = qv;
        }
        // stage k tile (negated)
        #pragma unroll
        for (int t = 0; t < 8; t++) {
            int i = tid + t * 64;
            int c = i >> 3, col = i & 7;
            int gk = kt + col * 4;
            float4 kv = make_float4(0.f, 0.f, 0.f, 0.f);
            if (gk < NN) kv = *(const float4*)&kb[(size_t)(cc + c) * NN + gk];
            float* kr = &kS[c * DLD + col * 4];
            kr[0] = -kv.x; kr[1] = -kv.y; kr[2] = -kv.z; kr[3] = -kv.w;
        }
        __syncthreads();

        #pragma unroll 4
        for (int c = 0; c < DCS; c++) {
            float4 qv = *(const float4*)&qS[c * DLD + tx * 4];
            ull qp0 = ((const ull*)&qv)[0];
            ull qp1 = ((const ull*)&qv)[1];
            float4 kv = *(const float4*)&kS[c * DLD + ty * 4];
            ull nk[4];
            asm("mov.b64 %0, {%1, %1};" : "=l"(nk[0]) : "f"(kv.x));
            asm("mov.b64 %0, {%1, %1};" : "=l"(nk[1]) : "f"(kv.y));
            asm("mov.b64 %0, {%1, %1};" : "=l"(nk[2]) : "f"(kv.z));
            asm("mov.b64 %0, {%1, %1};" : "=l"(nk[3]) : "f"(kv.w));
            #pragma unroll
            for (int j = 0; j < 4; j++) {
                ull d0, d1;
                asm("fma.rn.f32x2 %0, %1, %2, %3;"
                    : "=l"(d0) : "l"(qp0), "l"(INVT2), "l"(nk[j]));
                asm("fma.rn.f32x2 %0, %1, %2, %3;"
                    : "=l"(d1) : "l"(qp1), "l"(INVT2), "l"(nk[j]));
                d0 &= ABS2MASK;
                d1 &= ABS2MASK;
                asm("fma.rn.f32x2 %0, %1, %2, %0;"
                    : "+l"(acc[j][0]) : "l"(d0), "l"(ONE2));
                asm("fma.rn.f32x2 %0, %1, %2, %0;"
                    : "+l"(acc[j][1]) : "l"(d1), "l"(ONE2));
            }
        }
        __syncthreads();
    }

    float* ab = attn + (size_t)b * NN * NN;
    const int gq = qt + tx * 4;   // 784 % 4 == 0 -> float4 all-valid or all-invalid
    if (gq < NN) {
        #pragma unroll
        for (int j = 0; j < 4; j++) {
            int gk = kt + ty * 4 + j;
            if (gk < NN) {
                float4 o;
                o.x = __uint_as_float((unsigned)(acc[j][0] & 0xffffffffu)) * INVC;
                o.y = __uint_as_float((unsigned)(acc[j][0] >> 32))         * INVC;
                o.z = __uint_as_float((unsigned)(acc[j][1] & 0xffffffffu)) * INVC;
                o.w = __uint_as_float((unsigned)(acc[j][1] >> 32))         * INVC;
                *(float4*)&ab[(size_t)gk * NN + gq] = o;
            }
        }
    }
}

// ================= Softmax over last dim (q), in place ========================
__global__ __launch_bounds__(256) void softmax_kernel(float* __restrict__ attn) {
    __shared__ float red[8];
    const int row = blockIdx.x;
    float* p = attn + (size_t)row * NN;
    const int tid  = threadIdx.x;
    const bool act = (tid < NN / 4);   // 196 active lanes

    float4 v = make_float4(-1e30f, -1e30f, -1e30f, -1e30f);
    if (act) v = ((const float4*)p)[tid];

    float mx = fmaxf(fmaxf(v.x, v.y), fmaxf(v.z, v.w));
    #pragma unroll
    for (int o = 16; o > 0; o >>= 1) mx = fmaxf(mx, __shfl_xor_sync(0xffffffffu, mx, o));
    if ((tid & 31) == 0) red[tid >> 5] = mx;
    __syncthreads();
    if (tid < 32) {
        float m = (tid < 8) ? red[tid] : -1e30f;
        #pragma unroll
        for (int o = 4; o > 0; o >>= 1) m = fmaxf(m, __shfl_xor_sync(0xffffffffu, m, o));
        if (tid == 0) red[0] = m;
    }
    __syncthreads();
    mx = red[0];
    __syncthreads();

    v.x = __expf(v.x - mx); v.y = __expf(v.y - mx);
    v.z = __expf(v.z - mx); v.w = __expf(v.w - mx);
    float s = act ? (v.x + v.y) + (v.z + v.w) : 0.f;
    #pragma unroll
    for (int o = 16; o > 0; o >>= 1) s += __shfl_xor_sync(0xffffffffu, s, o);
    if ((tid & 31) == 0) red[tid >> 5] = s;
    __syncthreads();
    if (tid < 32) {
        float m = (tid < 8) ? red[tid] : 0.f;
        #pragma unroll
        for (int o = 4; o > 0; o >>= 1) m += __shfl_xor_sync(0xffffffffu, m, o);
        if (tid == 0) red[0] = m;
    }
    __syncthreads();
    const float inv = 1.f / red[0];
    if (act) {
        v.x *= inv; v.y *= inv; v.z *= inv; v.w *= inv;
        ((float4*)p)[tid] = v;
    }
}

// ================= GEMM: out[b,c,k] = sum_q v[b,c,q] * attn[b,k,q] ============
#define GTHR   224
#define GTN    112
#define GBQ    16
#define NSPLIT 21
#define NCH    49          // 784/16 q-chunks
#define VLDg   132         // 128 + 4
#define ALDg   116         // 112 + 4
#define PTILE  (128 * 112) // 14336

__device__ float g_part[(size_t)B_ * NSPLIT * 7 * PTILE];

__global__ __launch_bounds__(GTHR) void gemm1_kernel(const float* __restrict__ v,
                                                     const float* __restrict__ attn) {
    __shared__ float vS[GBQ * VLDg];   // [q][c]
    __shared__ float aS[GBQ * ALDg];   // [q][k]
    const int ktile = blockIdx.x;      // 0..6
    const int s     = blockIdx.y;      // 0..20
    const int b     = blockIdx.z;
    const int tid = threadIdx.x;
    const int tx = tid % 28;           // k: tx*4 .. +3
    const int ty = tid / 28;           // c: ty*16 .. +15

    const float* vb = v    + (size_t)b * C_ * NN;
    const float* ab = attn + (size_t)b * NN * NN + (size_t)ktile * GTN * NN;

    ull acc[8][4];
    #pragma unroll
    for (int p = 0; p < 8; p++)
        #pragma unroll
        for (int j = 0; j < 4; j++) acc[p][j] = 0ULL;

    const int ch0 = (s * NCH) / NSPLIT;
    const int ch1 = ((s + 1) * NCH) / NSPLIT;

    for (int ch = ch0; ch < ch1; ch++) {
        const int q0 = ch * GBQ;
        for (int i = tid; i < 512; i += GTHR) {
            int c = i >> 2, q4 = i & 3;
            float4 t = *(const float4*)&vb[(size_t)c * NN + q0 + q4 * 4];
            vS[(q4 * 4 + 0) * VLDg + c] = t.x;
            vS[(q4 * 4 + 1) * VLDg + c] = t.y;
            vS[(q4 * 4 + 2) * VLDg + c] = t.z;
            vS[(q4 * 4 + 3) * VLDg + c] = t.w;
        }
        for (int i = tid; i < 448; i += GTHR) {
            int kk = i >> 2, q4 = i & 3;
            float4 t = *(const float4*)&ab[(size_t)kk * NN + q0 + q4 * 4];
            aS[(q4 * 4 + 0) * ALDg + kk] = t.x;
            aS[(q4 * 4 + 1) * ALDg + kk] = t.y;
            aS[(q4 * 4 + 2) * ALDg + kk] = t.z;
            aS[(q4 * 4 + 3) * ALDg + kk] = t.w;
        }
        __syncthreads();

        #pragma unroll 4
        for (int qq = 0; qq < GBQ; qq++) {
            float4 a4 = *(const float4*)&aS[qq * ALDg + tx * 4];
            ull d[4];
            asm("mov.b64 %0, {%1, %1};" : "=l"(d[0]) : "f"(a4.x));
            asm("mov.b64 %0, {%1, %1};" : "=l"(d[1]) : "f"(a4.y));
            asm("mov.b64 %0, {%1, %1};" : "=l"(d[2]) : "f"(a4.z));
            asm("mov.b64 %0, {%1, %1};" : "=l"(d[3]) : "f"(a4.w));
            const float* vrow = &vS[qq * VLDg + ty * 16];
            float4 v0 = *(const float4*)(vrow + 0);
            float4 v1 = *(const float4*)(vrow + 4);
            float4 v2 = *(const float4*)(vrow + 8);
            float4 v3 = *(const float4*)(vrow + 12);
            ull vp[8];
            vp[0] = ((const ull*)&v0)[0]; vp[1] = ((const ull*)&v0)[1];
            vp[2] = ((const ull*)&v1)[0]; vp[3] = ((const ull*)&v1)[1];
            vp[4] = ((const ull*)&v2)[0]; vp[5] = ((const ull*)&v2)[1];
            vp[6] = ((const ull*)&v3)[0]; vp[7] = ((const ull*)&v3)[1];
            #pragma unroll
            for (int p = 0; p < 8; p++) {
                #pragma unroll
                for (int j = 0; j < 4; j++)
                    asm("fma.rn.f32x2 %0, %1, %2, %0;"
                        : "+l"(acc[p][j]) : "l"(vp[p]), "l"(d[j]));
            }
        }
        __syncthreads();
    }

    float* base = g_part + (((size_t)(b * NSPLIT + s) * 7) + ktile) * PTILE;
    #pragma unroll
    for (int p = 0; p < 8; p++) {
        int c0 = ty * 16 + p * 2;
        float4 lo, hi;
        lo.x = __uint_as_float((unsigned)(acc[p][0] & 0xffffffffu));
        lo.y = __uint_as_float((unsigned)(acc[p][1] & 0xffffffffu));
        lo.z = __uint_as_float((unsigned)(acc[p][2] & 0xffffffffu));
        lo.w = __uint_as_float((unsigned)(acc[p][3] & 0xffffffffu));
        hi.x = __uint_as_float((unsigned)(acc[p][0] >> 32));
        hi.y = __uint_as_float((unsigned)(acc[p][1] >> 32));
        hi.z = __uint_as_float((unsigned)(acc[p][2] >> 32));
        hi.w = __uint_as_float((unsigned)(acc[p][3] >> 32));
        *(float4*)&base[(size_t)c0 * GTN + tx * 4]       = lo;
        *(float4*)&base[(size_t)(c0 + 1) * GTN + tx * 4] = hi;
    }
}

__global__ __launch_bounds__(256) void gemm2_kernel(float* __restrict__ out) {
    const int idx = blockIdx.x * 256 + threadIdx.x;   // float4 index
    const int total4 = B_ * C_ * NN / 4;              // 50176
    if (idx >= total4) return;
    const int per_b = C_ * NN / 4;
    const int b = idx / per_b;
    const int e = (idx % per_b) * 4;
    const int c  = e / NN;
    const int kk = e % NN;
    const int kt = kk / GTN, kl = kk % GTN;
    const float* src = g_part + (((size_t)(b * NSPLIT) * 7) + kt) * PTILE
                     + (size_t)c * GTN + kl;
    float4 s = make_float4(0.f, 0.f, 0.f, 0.f);
    #pragma unroll
    for (int sp = 0; sp < NSPLIT; sp++) {
        float4 t = *(const float4*)(src + (size_t)sp * 7 * PTILE);
        s.x += t.x; s.y += t.y; s.z += t.z; s.w += t.w;
    }
    ((float4*)out)[idx] = s;
}

// ================= Launch ======================================================
extern "C" void kernel_launch(void* const* d_in, const int* in_sizes, int n_in,
                              void* d_out, int out_size) {
    const float* q = (const float*)d_in[0];
    const float* k = (const float*)d_in[1];
    const float* v = (const float*)d_in[2];
    float* out  = (float*)d_out;                      // [B, C, N]
    float* attn = out + (size_t)B_ * C_ * NN;         // [B, N, N]

    (void)in_sizes; (void)n_in; (void)out_size;

    // 1) L1 distance logits -> attn region (25 x 25 x 2 = 1250 blocks)
    dim3 dgrid((NN + DQT - 1) / DQT, (NN + DKT - 1) / DKT, B_);
    dist_kernel<<<dgrid, 64>>>(q, k, attn);

    // 2) softmax over q, in place
    softmax_kernel<<<B_ * NN, 256>>>(attn);

    // 3) out = v @ attn^T : split-q partials, then reduce
    dim3 g1(7, NSPLIT, B_);                           // 294 blocks
    gemm1_kernel<<<g1, GTHR>>>(v, attn);
    gemm2_kernel<<<(B_ * C_ * NN / 4 + 255) / 256, 256>>>(out);
}